// round 14
// baseline (speedup 1.0000x reference)
#include <cuda_runtime.h>
#include <cuda_bf16.h>
#include <cuda_fp16.h>
#include <math.h>
#include <stdint.h>

#define BATCH 512
#define MDIM  256
#define NCOLS 512

#define BM 128
#define BN 256
#define BK 32           // two 16-wide k-groups per barrier interval
#define STG 3
#define SPLIT 18        // split-K CTAs per modality -> 4*2*18 = 144 CTAs
#define NCTA 144
#define NTHR 256        // 8 warps: 2(m) x 4(n), warp tile 64x64
#define NUNITS (3 * BATCH)

#define AST16 (BM * 16)           // A sub-tile (one k-group): 2048 floats
#define BST16 (BN * 16)           // B sub-tile: 4096 floats
#define AST   (2 * AST16)         // per stage
#define BST   (2 * BST16)

#define LOG2E 1.4426950408889634f
#define LN2   0.6931471805599453f

__device__ float g_P[3][BATCH][NCOLS];      // projections (atomic-accumulated)
__device__ float g_partial[3][2][BATCH];    // per-head partial dots
__device__ int   g_done;                    // attn unit completion counter
__device__ int   g_gemm_done;               // gemm CTA completion counter
__device__ int   g_bcnt[BATCH];             // per-batch attn-unit counters

// ---------------------------------------------------------------------------
// helpers
// ---------------------------------------------------------------------------
__device__ __forceinline__ uint32_t smem_u32(const void* p) {
    uint32_t a;
    asm("{ .reg .u64 t; cvta.to.shared.u64 t, %1; cvt.u32.u64 %0, t; }" : "=r"(a) : "l"(p));
    return a;
}
__device__ __forceinline__ void cpa16(float* dst, const float* src, int nb) {
    asm volatile("cp.async.cg.shared.global [%0], [%1], 16, %2;"
                 :: "r"(smem_u32(dst)), "l"(src), "r"(nb) : "memory");
}
__device__ __forceinline__ uint32_t pk(uint32_t lo, uint32_t hi) {
    uint32_t d;
    asm("cvt.rn.f16x2.f32 %0, %1, %2;"
        : "=r"(d) : "f"(__uint_as_float(hi)), "f"(__uint_as_float(lo)));
    return d;
}
__device__ __forceinline__ void mma_f16(float* d, uint32_t a0, uint32_t a1,
                                        uint32_t a2, uint32_t a3,
                                        uint32_t b0, uint32_t b1) {
    asm volatile(
        "mma.sync.aligned.m16n8k16.row.col.f32.f16.f16.f32 "
        "{%0,%1,%2,%3}, {%4,%5,%6,%7}, {%8,%9}, {%0,%1,%2,%3};"
        : "+f"(d[0]), "+f"(d[1]), "+f"(d[2]), "+f"(d[3])
        : "r"(a0), "r"(a1), "r"(a2), "r"(a3), "r"(b0), "r"(b1));
}
__device__ __forceinline__ float ex2f(float x) {
    float y; asm("ex2.approx.f32 %0, %1;" : "=f"(y) : "f"(x)); return y;
}
__device__ __forceinline__ __half2 h2ex2(__half2 x) {
    uint32_t xi = *reinterpret_cast<uint32_t*>(&x), yi;
    asm("ex2.approx.f16x2 %0, %1;" : "=r"(yi) : "r"(xi));
    return *reinterpret_cast<__half2*>(&yi);
}

__device__ __forceinline__ float block_reduce_sum(float v, float* red) {
#pragma unroll
    for (int o = 16; o; o >>= 1) v += __shfl_xor_sync(0xffffffffu, v, o);
    const int t = threadIdx.x;
    __syncthreads();
    if ((t & 31) == 0) red[t >> 5] = v;
    __syncthreads();
    if (t == 0) {
        float s = 0.f;
#pragma unroll
        for (int i = 0; i < 8; ++i) s += red[i];
        v = s;
    }
    return v;
}

// ---------------------------------------------------------------------------
// stage loader: A tile 128x32, B tile 256x32, two 16-wide k-group sub-tiles
// ---------------------------------------------------------------------------
__device__ __forceinline__ void load_stage(
    const float* __restrict__ A, const float* __restrict__ W,
    int K, int mt, int kt, float* As, float* Bs, int tid)
{
#pragma unroll
    for (int h = 0; h < 4; ++h) {                 // A: 1024 16B chunks
        const int ch  = tid + h * NTHR;
        const int row = ch >> 3, kc = ch & 7;
        const int g   = kc >> 2, kcc = kc & 3;
        const int k   = kt + kc * 4;
        int nb = (K - k) * 4; nb = nb < 0 ? 0 : (nb > 16 ? 16 : nb);
        const int ks = (k < K) ? k : 0;
        cpa16(As + g * AST16 + row * 16 + kcc * 4,
              A + (size_t)(mt * BM + row) * K + ks, nb);
    }
#pragma unroll
    for (int h = 0; h < 8; ++h) {                 // B: 2048 chunks
        const int ch  = tid + h * NTHR;
        const int row = ch >> 3, kc = ch & 7;
        const int g   = kc >> 2, kcc = kc & 3;
        const int k   = kt + kc * 4;
        int nb = (K - k) * 4; nb = nb < 0 ? 0 : (nb > 16 ? 16 : nb);
        const int ks = (k < K) ? k : 0;
        cpa16(Bs + g * BST16 + row * 16 + kcc * 4,
              W + (size_t)row * K + ks, nb);
    }
}

// ---------------------------------------------------------------------------
// one attention unit (batch b, pair): identical math to R12/R13 attn blocks.
// smem carved from the dynamic buffer. Ends with the g_done/final-head logic
// and the per-batch g_P re-zeroing for the next graph replay.
// ---------------------------------------------------------------------------
__device__ void attn_unit(int b, int pair, float* smf,
                          const float* __restrict__ W3e,
                          const float* __restrict__ W3m,
                          const float* __restrict__ W3c,
                          const float* __restrict__ b3e,
                          const float* __restrict__ b3m,
                          const float* __restrict__ b3c,
                          float* __restrict__ out)
{
    const int t = threadIdx.x;

    float2*  sa    = reinterpret_cast<float2*>(smf);              // 256 float2
    float2*  sb    = sa + MDIM;                                   // 256 float2
    float*   xbuf  = reinterpret_cast<float*>(sb + MDIM);         // 256*17
    float*   red   = xbuf + 256 * 17;                             // 8
    __half2* pax   = reinterpret_cast<__half2*>(red + 8);
    __half2* pay   = pax + 128;
    __half2* pbx   = pay + 128;
    __half2* pby   = pbx + 128;
    __half2* prinv = pby + 128;
    int*     sfl   = reinterpret_cast<int*>(prinv + 128);         // [0]=slast [1]=szero

    const int ai = (pair == 2) ? 1 : 0;          // e,e,m
    const int bi = (pair == 0) ? 1 : 2;          // m,c,c

    __syncthreads();   // smem reuse boundary (previous unit / gemm stage)
    {
        const float* Pa = &g_P[ai][b][0];
        float px = Pa[t], py = Pa[MDIM + t];
        float inv = rsqrtf(px * px + py * py) * LOG2E;
        sa[t] = make_float2(px * inv, py * inv);

        const float* Pb = &g_P[bi][b][0];
        px = Pb[t]; py = Pb[MDIM + t];
        inv = rsqrtf(px * px + py * py);
        sb[t] = make_float2(px * inv, py * inv);
    }
    __syncthreads();

    const __half2 hz = __float2half2_rn(0.f);

    if (pair < 2) {
        const int ti = t >> 4;
        const int tj = t & 15;

        __half2 bx2[8], by2[8];
#pragma unroll
        for (int k = 0; k < 8; ++k) {
            float2 b0 = sb[tj * 16 + 2 * k];
            float2 b1 = sb[tj * 16 + 2 * k + 1];
            bx2[k] = __floats2half2_rn(b0.x, b1.x);
            by2[k] = __floats2half2_rn(b0.y, b1.y);
        }

        __half2 cd2[8], cn02[8], cn12[8];
#pragma unroll
        for (int k = 0; k < 8; ++k) { cd2[k] = hz; cn02[k] = hz; cn12[k] = hz; }

        float rowd = 0.f, rown0 = 0.f, rown1 = 0.f;

#pragma unroll
        for (int ri = 0; ri < 16; ++ri) {
            const float2 av = sa[ti * 16 + ri];
            const __half2 ax2 = __float2half2_rn(av.x);
            const __half2 ay2 = __float2half2_rn(av.y);
            __half2 rd2 = hz, rn02 = hz, rn12 = hz;
#pragma unroll
            for (int k = 0; k < 8; ++k) {
                const __half2 d2 = __hfma2(ay2, by2[k], __hmul2(ax2, bx2[k]));
                const __half2 X2 = h2ex2(d2);
                cd2[k]  = __hadd2(cd2[k], X2);
                cn02[k] = __hfma2(ax2, X2, cn02[k]);
                cn12[k] = __hfma2(ay2, X2, cn12[k]);
                rd2  = __hadd2(rd2, X2);
                rn02 = __hfma2(bx2[k], X2, rn02);
                rn12 = __hfma2(by2[k], X2, rn12);
            }
            float2 f0 = __half22float2(rd2);
            float2 f1 = __half22float2(rn02);
            float2 f2 = __half22float2(rn12);
            float rd = f0.x + f0.y, rn0 = f1.x + f1.y, rn1 = f2.x + f2.y;
#pragma unroll
            for (int o = 1; o < 16; o <<= 1) {
                rd  += __shfl_xor_sync(0xffffffffu, rd,  o);
                rn0 += __shfl_xor_sync(0xffffffffu, rn0, o);
                rn1 += __shfl_xor_sync(0xffffffffu, rn1, o);
            }
            if (ri == tj) { rowd = rd; rown0 = rn0; rown1 = rn1; }
        }

        float cd[16], cn0[16], cn1[16];
#pragma unroll
        for (int k = 0; k < 8; ++k) {
            float2 f;
            f = __half22float2(cd2[k]);  cd[2*k] = f.x;  cd[2*k+1] = f.y;
            f = __half22float2(cn02[k]); cn0[2*k] = f.x; cn0[2*k+1] = f.y;
            f = __half22float2(cn12[k]); cn1[2*k] = f.x; cn1[2*k+1] = f.y;
        }

        {
            const float* WB = (pair == 0) ? W3m : W3c;
            float v = (rown0 * WB[t] + rown1 * WB[MDIM + t]) / rowd;
            v = block_reduce_sum(v, red);
            if (t == 0) {
                if (pair == 0) g_partial[1][0][b] = v;
                else           g_partial[2][0][b] = v;
            }
        }

        float d = 0.f, n0 = 0.f, n1 = 0.f;
#pragma unroll 1
        for (int ph = 0; ph < 3; ++ph) {
            __syncthreads();
#pragma unroll
            for (int jl = 0; jl < 16; ++jl)
                xbuf[t * 17 + jl] = (ph == 0) ? cd[jl] : (ph == 1 ? cn0[jl] : cn1[jl]);
            __syncthreads();
            float s = 0.f;
#pragma unroll
            for (int tp = 0; tp < 16; ++tp)
                s += xbuf[(tp * 16 + (t >> 4)) * 17 + (t & 15)];
            if (ph == 0) d = s; else if (ph == 1) n0 = s; else n1 = s;
        }
        {
            const float* WA = W3e + (pair == 0 ? 0 : 512);
            float v = LN2 * (n0 * WA[t] + n1 * WA[MDIM + t]) / d;
            v = block_reduce_sum(v, red);
            if (t == 0) g_partial[0][pair][b] = v;
        }
    } else {
        if (t < 128) {
            float2 a0 = sa[2 * t], a1 = sa[2 * t + 1];
            pax[t] = __floats2half2_rn(a0.x, a1.x);
            pay[t] = __floats2half2_rn(a0.y, a1.y);
            float2 b0 = sb[2 * t], b1 = sb[2 * t + 1];
            pbx[t] = __floats2half2_rn(b0.x, b1.x);
            pby[t] = __floats2half2_rn(b0.y, b1.y);
        }
        __syncthreads();

        {
            const __half2 ax2 = __float2half2_rn(sa[t].x);
            const __half2 ay2 = __float2half2_rn(sa[t].y);
            float d = 0.f, n0 = 0.f, n1 = 0.f;
#pragma unroll 2
            for (int ko = 0; ko < 16; ++ko) {
                __half2 d2 = hz, n02 = hz, n12 = hz;
#pragma unroll
                for (int ki = 0; ki < 8; ++ki) {
                    const int k = ko * 8 + ki;
                    const __half2 e2 = __hfma2(ay2, pby[k], __hmul2(ax2, pbx[k]));
                    const __half2 X2 = h2ex2(e2);
                    d2  = __hadd2(d2, X2);
                    n02 = __hfma2(pbx[k], X2, n02);
                    n12 = __hfma2(pby[k], X2, n12);
                }
                float2 f;
                f = __half22float2(d2);  d  += f.x + f.y;
                f = __half22float2(n02); n0 += f.x + f.y;
                f = __half22float2(n12); n1 += f.x + f.y;
            }
            const float id = 1.0f / d;
            reinterpret_cast<__half*>(prinv)[t] = __float2half(id);
            float v = (n0 * W3c[512 + t] + n1 * W3c[768 + t]) * id;
            v = block_reduce_sum(v, red);
            if (t == 0) g_partial[2][1][b] = v;
        }
        {
            const __half2 cx2 = __float2half2_rn(sb[t].x);
            const __half2 cy2 = __float2half2_rn(sb[t].y);
            float n0 = 0.f, n1 = 0.f;
#pragma unroll 2
            for (int ko = 0; ko < 16; ++ko) {
                __half2 n02 = hz, n12 = hz;
#pragma unroll
                for (int ki = 0; ki < 8; ++ki) {
                    const int k = ko * 8 + ki;
                    const __half2 e2 = __hfma2(pay[k], cy2, __hmul2(pax[k], cx2));
                    const __half2 X2 = __hmul2(h2ex2(e2), prinv[k]);
                    n02 = __hfma2(pax[k], X2, n02);
                    n12 = __hfma2(pay[k], X2, n12);
                }
                float2 f;
                f = __half22float2(n02); n0 += f.x + f.y;
                f = __half22float2(n12); n1 += f.x + f.y;
            }
            float v = LN2 * (n0 * W3m[512 + t] + n1 * W3m[768 + t]);
            v = block_reduce_sum(v, red);
            if (t == 0) g_partial[1][1][b] = v;
        }
    }

    // ---- per-batch g_P re-zero (for next replay) + final head by last unit
    __syncthreads();
    __threadfence();
    if (t == 0) {
        sfl[1] = (atomicAdd(&g_bcnt[b], 1) == 2) ? 1 : 0;
        int tk = atomicAdd(&g_done, 1);
        sfl[0] = (tk == NUNITS - 1) ? 1 : 0;
    }
    __syncthreads();
    if (sfl[1]) {
        // all 3 units of batch b have finished their reads of g_P[*][b][*]
#pragma unroll
        for (int md = 0; md < 3; ++md) {
            float2* p = reinterpret_cast<float2*>(&g_P[md][b][0]);
            p[t] = make_float2(0.f, 0.f);
        }
        if (t == 0) g_bcnt[b] = 0;
    }
    if (sfl[0]) {
        __threadfence();
#pragma unroll
        for (int q = 0; q < 2; ++q) {
            const int bb = t + q * 256;
            const float xe = g_partial[0][0][bb] + g_partial[0][1][bb] + b3e[0];
            const float xm = g_partial[1][0][bb] + g_partial[1][1][bb] + b3m[0];
            const float xc = g_partial[2][0][bb] + g_partial[2][1][bb] + b3c[0];
            out[bb]             = 1.0f / (1.0f + expf(-xe));
            out[BATCH + bb]     = 1.0f / (1.0f + expf(-xm));
            out[2 * BATCH + bb] = 1.0f / (1.0f + expf(-xc));
        }
        if (t == 0) { g_done = 0; g_gemm_done = 0; }
    }
    __syncthreads();
}

// ---------------------------------------------------------------------------
// Persistent kernel: fp16 mma.sync GEMM (3 modalities) -> device gate ->
// attention units -> final head. 144 CTAs = exactly one wave (spin-safe).
// ---------------------------------------------------------------------------
__global__ __launch_bounds__(NTHR, 1)
void moma_kernel(const float* __restrict__ e, const float* __restrict__ m,
                 const float* __restrict__ c,
                 const float* __restrict__ Wex, const float* __restrict__ Wey,
                 const float* __restrict__ Wmx, const float* __restrict__ Wmy,
                 const float* __restrict__ Wcx, const float* __restrict__ Wcy,
                 const float* __restrict__ W3e, const float* __restrict__ W3m,
                 const float* __restrict__ W3c,
                 const float* __restrict__ b3e, const float* __restrict__ b3m,
                 const float* __restrict__ b3c, float* __restrict__ out,
                 int K0, int K1, int K2)
{
    const int mt = blockIdx.x;
    const int nt = blockIdx.y;
    const int sp = blockIdx.z;
    const int cta = mt + 4 * (nt + 2 * sp);   // 0..143

    extern __shared__ float smf[];
    float* As = smf;                          // [STG][AST]
    float* Bs = smf + STG * AST;              // [STG][BST]

    const int tid  = threadIdx.x;
    const int lane = tid & 31;
    const int wid  = tid >> 5;
    const int wm   = (wid & 1) * 64;          // warp grid 2(m) x 4(n)
    const int wn   = (wid >> 1) * 64;
    const int r    = lane >> 2;
    const int cq   = lane & 3;

    // ===================== GEMM phase =====================
#pragma unroll 1
    for (int mod = 0; mod < 3; ++mod) {
        const float* A = (mod == 0) ? e : (mod == 1 ? m : c);
        const float* W;
        if (mod == 0) W = nt ? Wey : Wex;
        else if (mod == 1) W = nt ? Wmy : Wmx;
        else W = nt ? Wcy : Wcx;
        const int K = (mod == 0) ? K0 : (mod == 1 ? K1 : K2);

        const int nk  = (K + BK - 1) / BK;
        const int per = (nk + SPLIT - 1) / SPLIT;
        const int i0  = sp * per;
        const int i1  = min(nk, i0 + per);
        const int n   = i1 - i0;
        if (n <= 0) { __syncthreads(); continue; }

        float acc[4][8][4];
#pragma unroll
        for (int a = 0; a < 4; ++a)
#pragma unroll
            for (int b = 0; b < 8; ++b)
#pragma unroll
                for (int q = 0; q < 4; ++q) acc[a][b][q] = 0.f;

#pragma unroll
        for (int s = 0; s < STG - 1; ++s) {
            if (s < n) load_stage(A, W, K, mt, (i0 + s) * BK,
                                  As + s * AST, Bs + s * BST, tid);
            asm volatile("cp.async.commit_group;" ::: "memory");
        }

#pragma unroll 1
        for (int it = 0; it < n; ++it) {
            asm volatile("cp.async.wait_group %0;" :: "n"(STG - 2) : "memory");
            __syncthreads();

            if (it + STG - 1 < n) {
                const int ws = (it + STG - 1) % STG;
                load_stage(A, W, K, mt, (i0 + it + STG - 1) * BK,
                           As + ws * AST, Bs + ws * BST, tid);
            }
            asm volatile("cp.async.commit_group;" ::: "memory");

            const int s = it % STG;

#pragma unroll
            for (int g = 0; g < 2; ++g) {
                const float* Ab = As + s * AST + g * AST16;
                const float* Bb = Bs + s * BST + g * BST16;

                uint4 alo[4], ahi[4], bv[8];
#pragma unroll
                for (int mi = 0; mi < 4; ++mi) {
                    const float* ap = Ab + (wm + mi * 16 + r) * 16 + cq * 4;
                    alo[mi] = *reinterpret_cast<const uint4*>(ap);
                    ahi[mi] = *reinterpret_cast<const uint4*>(ap + 8 * 16);
                }
#pragma unroll
                for (int ni = 0; ni < 8; ++ni) {
                    const float* bp = Bb + (wn + ni * 8 + r) * 16 + cq * 4;
                    bv[ni] = *reinterpret_cast<const uint4*>(bp);
                }

                uint32_t af[4][4], bf[8][2];
#pragma unroll
                for (int mi = 0; mi < 4; ++mi) {
                    af[mi][0] = pk(alo[mi].x, alo[mi].y);
                    af[mi][1] = pk(ahi[mi].x, ahi[mi].y);
                    af[mi][2] = pk(alo[mi].z, alo[mi].w);
                    af[mi][3] = pk(ahi[mi].z, ahi[mi].w);
                }
#pragma unroll
                for (int ni = 0; ni < 8; ++ni) {
                    bf[ni][0] = pk(bv[ni].x, bv[ni].y);
                    bf[ni][1] = pk(bv[ni].z, bv[ni].w);
                }

#pragma unroll
                for (int mi = 0; mi < 4; ++mi)
#pragma unroll
                    for (int ni = 0; ni < 8; ++ni)
                        mma_f16(acc[mi][ni], af[mi][0], af[mi][1], af[mi][2], af[mi][3],
                                bf[ni][0], bf[ni][1]);
            }
        }

        asm volatile("cp.async.wait_group 0;" ::: "memory");
        __syncthreads();

        float* Cb = &g_P[mod][0][0];
#pragma unroll
        for (int mi = 0; mi < 4; ++mi) {
            const int row = mt * BM + wm + mi * 16 + r;
#pragma unroll
            for (int ni = 0; ni < 8; ++ni) {
                const int col = nt * BN + wn + ni * 8 + cq * 2;
                float* p0 = Cb + (size_t)row * NCOLS + col;
                float* p1 = p0 + 8 * NCOLS;
                asm volatile("red.global.add.v2.f32 [%0], {%1, %2};"
                             :: "l"(p0), "f"(acc[mi][ni][0]), "f"(acc[mi][ni][1]) : "memory");
                asm volatile("red.global.add.v2.f32 [%0], {%1, %2};"
                             :: "l"(p1), "f"(acc[mi][ni][2]), "f"(acc[mi][ni][3]) : "memory");
            }
        }
    }

    // ===================== device-wide gate =====================
    if (tid == 0) {
        __threadfence();
        atomicAdd(&g_gemm_done, 1);
        while (atomicAdd(&g_gemm_done, 0) < NCTA) __nanosleep(64);
    }
    __syncthreads();

    // ===================== attention phase =====================
#pragma unroll 1
    for (int u = cta; u < NUNITS; u += NCTA) {
        const int pair = u >> 9;        // u / 512
        const int b    = u & 511;       // u % 512
        attn_unit(b, pair, smf, W3e, W3m, W3c, b3e, b3m, b3c, out);
    }
}

// ---------------------------------------------------------------------------
// Launch
// ---------------------------------------------------------------------------
extern "C" void kernel_launch(void* const* d_in, const int* in_sizes, int n_in,
                              void* d_out, int out_size)
{
    const float* expr = (const float*)d_in[0];
    const float* mut  = (const float*)d_in[1];
    const float* cna  = (const float*)d_in[2];
    const float* Wex  = (const float*)d_in[3];
    const float* Wey  = (const float*)d_in[4];
    const float* Wmx  = (const float*)d_in[5];
    const float* Wmy  = (const float*)d_in[6];
    const float* Wcx  = (const float*)d_in[7];
    const float* Wcy  = (const float*)d_in[8];
    const float* W3e  = (const float*)d_in[9];
    const float* b3e  = (const float*)d_in[10];
    const float* W3m  = (const float*)d_in[11];
    const float* b3m  = (const float*)d_in[12];
    const float* W3c  = (const float*)d_in[13];
    const float* b3c  = (const float*)d_in[14];

    const int K1 = in_sizes[0] / BATCH;   // 20000
    const int K2 = in_sizes[1] / BATCH;   // 15000
    const int K3 = in_sizes[2] / BATCH;   // 20000

    const int SMEM = STG * (AST + BST) * 4;   // 3 * 48KB = 147456 B
    static bool attr_set = false;
    if (!attr_set) {
        cudaFuncSetAttribute(moma_kernel, cudaFuncAttributeMaxDynamicSharedMemorySize, SMEM);
        attr_set = true;
    }

    moma_kernel<<<dim3(4, 2, SPLIT), NTHR, SMEM>>>(
        expr, mut, cna, Wex, Wey, Wmx, Wmy, Wcx, Wcy,
        W3e, W3m, W3c, b3e, b3m, b3c, (float*)d_out, K1, K2, K3);
}

// round 15
// speedup vs baseline: 1.1746x; 1.1746x over previous
#include <cuda_runtime.h>
#include <cuda_bf16.h>
#include <cuda_fp16.h>
#include <math.h>
#include <stdint.h>

#define BATCH 512
#define MDIM  256
#define NCOLS 512

#define BM 128
#define BN 256
#define BK 32           // two 16-wide k-groups per barrier interval
#define STG 3
#define SPLIT 18        // split-K CTAs per modality -> 4*2*18 = 144 CTAs
#define NTHR 256        // 8 warps: 2(m) x 4(n), warp tile 64x64
#define NUNITS (3 * BATCH)

#define AST16 (BM * 16)           // A sub-tile (one k-group): 2048 floats
#define BST16 (BN * 16)           // B sub-tile: 4096 floats
#define AST   (2 * AST16)         // per stage
#define BST   (2 * BST16)

#define LOG2E 1.4426950408889634f
#define LN2   0.6931471805599453f

__device__ float g_P[3][BATCH][NCOLS];      // projections (atomic-accumulated; zero-init at load)
__device__ float g_partial[3][2][BATCH];    // per-head partial dots
__device__ int   g_done;                    // attn block completion counter
__device__ int   g_bcnt[BATCH];             // per-batch attn completion counters

// ---------------------------------------------------------------------------
// helpers
// ---------------------------------------------------------------------------
__device__ __forceinline__ uint32_t smem_u32(const void* p) {
    uint32_t a;
    asm("{ .reg .u64 t; cvta.to.shared.u64 t, %1; cvt.u32.u64 %0, t; }" : "=r"(a) : "l"(p));
    return a;
}
__device__ __forceinline__ void cpa16(float* dst, const float* src, int nb) {
    asm volatile("cp.async.cg.shared.global [%0], [%1], 16, %2;"
                 :: "r"(smem_u32(dst)), "l"(src), "r"(nb) : "memory");
}
// pack two f32 into f16x2: low half = lo (lower k index), high half = hi
__device__ __forceinline__ uint32_t pk(uint32_t lo, uint32_t hi) {
    uint32_t d;
    asm("cvt.rn.f16x2.f32 %0, %1, %2;"
        : "=r"(d) : "f"(__uint_as_float(hi)), "f"(__uint_as_float(lo)));
    return d;
}
__device__ __forceinline__ void mma_f16(float* d, uint32_t a0, uint32_t a1,
                                        uint32_t a2, uint32_t a3,
                                        uint32_t b0, uint32_t b1) {
    asm volatile(
        "mma.sync.aligned.m16n8k16.row.col.f32.f16.f16.f32 "
        "{%0,%1,%2,%3}, {%4,%5,%6,%7}, {%8,%9}, {%0,%1,%2,%3};"
        : "+f"(d[0]), "+f"(d[1]), "+f"(d[2]), "+f"(d[3])
        : "r"(a0), "r"(a1), "r"(a2), "r"(a3), "r"(b0), "r"(b1));
}
__device__ __forceinline__ float ex2f(float x) {
    float y; asm("ex2.approx.f32 %0, %1;" : "=f"(y) : "f"(x)); return y;
}
__device__ __forceinline__ __half2 h2ex2(__half2 x) {
    uint32_t xi = *reinterpret_cast<uint32_t*>(&x), yi;
    asm("ex2.approx.f16x2 %0, %1;" : "=r"(yi) : "r"(xi));
    return *reinterpret_cast<__half2*>(&yi);
}

// ---------------------------------------------------------------------------
// stage loader: A tile 128x32, B tile 256x32, two 16-wide k-group sub-tiles
// ---------------------------------------------------------------------------
__device__ __forceinline__ void load_stage(
    const float* __restrict__ A, const float* __restrict__ W,
    int K, int mt, int kt, float* As, float* Bs, int tid)
{
#pragma unroll
    for (int h = 0; h < 4; ++h) {                 // A: 1024 16B chunks
        const int ch  = tid + h * NTHR;
        const int row = ch >> 3, kc = ch & 7;
        const int g   = kc >> 2, kcc = kc & 3;
        const int k   = kt + kc * 4;
        int nb = (K - k) * 4; nb = nb < 0 ? 0 : (nb > 16 ? 16 : nb);
        const int ks = (k < K) ? k : 0;
        cpa16(As + g * AST16 + row * 16 + kcc * 4,
              A + (size_t)(mt * BM + row) * K + ks, nb);
    }
#pragma unroll
    for (int h = 0; h < 8; ++h) {                 // B: 2048 chunks
        const int ch  = tid + h * NTHR;
        const int row = ch >> 3, kc = ch & 7;
        const int g   = kc >> 2, kcc = kc & 3;
        const int k   = kt + kc * 4;
        int nb = (K - k) * 4; nb = nb < 0 ? 0 : (nb > 16 ? 16 : nb);
        const int ks = (k < K) ? k : 0;
        cpa16(Bs + g * BST16 + row * 16 + kcc * 4,
              W + (size_t)row * K + ks, nb);
    }
}

// ---------------------------------------------------------------------------
// fp16 mma.sync GEMM (m16n8k16, fp32 accum), 128x256 CTA tile, BK=32
// ---------------------------------------------------------------------------
__global__ __launch_bounds__(NTHR, 1)
void gemm_mma(const float* __restrict__ e, const float* __restrict__ m,
              const float* __restrict__ c,
              const float* __restrict__ Wex, const float* __restrict__ Wey,
              const float* __restrict__ Wmx, const float* __restrict__ Wmy,
              const float* __restrict__ Wcx, const float* __restrict__ Wcy,
              int K0, int K1, int K2)
{
    const int mt = blockIdx.x;
    const int nt = blockIdx.y;
    const int sp = blockIdx.z;

    extern __shared__ float smf[];
    float* As = smf;                          // [STG][AST]
    float* Bs = smf + STG * AST;              // [STG][BST]

    const int tid  = threadIdx.x;
    const int lane = tid & 31;
    const int wid  = tid >> 5;
    const int wm   = (wid & 1) * 64;          // warp grid 2(m) x 4(n)
    const int wn   = (wid >> 1) * 64;
    const int r    = lane >> 2;
    const int cq   = lane & 3;

#pragma unroll 1
    for (int mod = 0; mod < 3; ++mod) {
        const float* A = (mod == 0) ? e : (mod == 1 ? m : c);
        const float* W;
        if (mod == 0) W = nt ? Wey : Wex;
        else if (mod == 1) W = nt ? Wmy : Wmx;
        else W = nt ? Wcy : Wcx;
        const int K = (mod == 0) ? K0 : (mod == 1 ? K1 : K2);

        const int nk  = (K + BK - 1) / BK;
        const int per = (nk + SPLIT - 1) / SPLIT;
        const int i0  = sp * per;
        const int i1  = min(nk, i0 + per);
        const int n   = i1 - i0;
        if (n <= 0) { __syncthreads(); continue; }

        float acc[4][8][4];
#pragma unroll
        for (int a = 0; a < 4; ++a)
#pragma unroll
            for (int b = 0; b < 8; ++b)
#pragma unroll
                for (int q = 0; q < 4; ++q) acc[a][b][q] = 0.f;

#pragma unroll
        for (int s = 0; s < STG - 1; ++s) {
            if (s < n) load_stage(A, W, K, mt, (i0 + s) * BK,
                                  As + s * AST, Bs + s * BST, tid);
            asm volatile("cp.async.commit_group;" ::: "memory");
        }

#pragma unroll 1
        for (int it = 0; it < n; ++it) {
            asm volatile("cp.async.wait_group %0;" :: "n"(STG - 2) : "memory");
            __syncthreads();

            if (it + STG - 1 < n) {
                const int ws = (it + STG - 1) % STG;
                load_stage(A, W, K, mt, (i0 + it + STG - 1) * BK,
                           As + ws * AST, Bs + ws * BST, tid);
            }
            asm volatile("cp.async.commit_group;" ::: "memory");

            const int s = it % STG;

#pragma unroll
            for (int g = 0; g < 2; ++g) {
                const float* Ab = As + s * AST + g * AST16;
                const float* Bb = Bs + s * BST + g * BST16;

                uint4 alo[4], ahi[4], bv[8];
#pragma unroll
                for (int mi = 0; mi < 4; ++mi) {
                    const float* ap = Ab + (wm + mi * 16 + r) * 16 + cq * 4;
                    alo[mi] = *reinterpret_cast<const uint4*>(ap);
                    ahi[mi] = *reinterpret_cast<const uint4*>(ap + 8 * 16);
                }
#pragma unroll
                for (int ni = 0; ni < 8; ++ni) {
                    const float* bp = Bb + (wn + ni * 8 + r) * 16 + cq * 4;
                    bv[ni] = *reinterpret_cast<const uint4*>(bp);
                }

                uint32_t af[4][4], bf[8][2];
#pragma unroll
                for (int mi = 0; mi < 4; ++mi) {
                    af[mi][0] = pk(alo[mi].x, alo[mi].y);
                    af[mi][1] = pk(ahi[mi].x, ahi[mi].y);
                    af[mi][2] = pk(alo[mi].z, alo[mi].w);
                    af[mi][3] = pk(ahi[mi].z, ahi[mi].w);
                }
#pragma unroll
                for (int ni = 0; ni < 8; ++ni) {
                    bf[ni][0] = pk(bv[ni].x, bv[ni].y);
                    bf[ni][1] = pk(bv[ni].z, bv[ni].w);
                }

#pragma unroll
                for (int mi = 0; mi < 4; ++mi)
#pragma unroll
                    for (int ni = 0; ni < 8; ++ni)
                        mma_f16(acc[mi][ni], af[mi][0], af[mi][1], af[mi][2], af[mi][3],
                                bf[ni][0], bf[ni][1]);
            }
        }

        asm volatile("cp.async.wait_group 0;" ::: "memory");
        __syncthreads();

        float* Cb = &g_P[mod][0][0];
#pragma unroll
        for (int mi = 0; mi < 4; ++mi) {
            const int row = mt * BM + wm + mi * 16 + r;
#pragma unroll
            for (int ni = 0; ni < 8; ++ni) {
                const int col = nt * BN + wn + ni * 8 + cq * 2;
                float* p0 = Cb + (size_t)row * NCOLS + col;
                float* p1 = p0 + 8 * NCOLS;
                asm volatile("red.global.add.v2.f32 [%0], {%1, %2};"
                             :: "l"(p0), "f"(acc[mi][ni][0]), "f"(acc[mi][ni][1]) : "memory");
                asm volatile("red.global.add.v2.f32 [%0], {%1, %2};"
                             :: "l"(p1), "f"(acc[mi][ni][2]), "f"(acc[mi][ni][3]) : "memory");
            }
        }
    }
}

// ---------------------------------------------------------------------------
// block reduce (value valid on thread 0)
// ---------------------------------------------------------------------------
__device__ __forceinline__ float block_reduce_sum(float v, float* red) {
#pragma unroll
    for (int o = 16; o; o >>= 1) v += __shfl_xor_sync(0xffffffffu, v, o);
    const int t = threadIdx.x;
    __syncthreads();
    if ((t & 31) == 0) red[t >> 5] = v;
    __syncthreads();
    if (t == 0) {
        float s = 0.f;
#pragma unroll
        for (int i = 0; i < 8; ++i) s += red[i];
        v = s;
    }
    return v;
}

// ---------------------------------------------------------------------------
// Fused attention (R12 math, all pairs fp16x2). Additions vs R12:
//  - per-batch g_P re-zero for the next graph replay (last of the 3 units of
//    batch b zeroes g_P[*][b][*]; reads of g_P happen at unit start, the
//    counter increments after compute, so ordering is safe)
//  - last block overall runs the final sigmoid head and resets counters
// ---------------------------------------------------------------------------
__global__ __launch_bounds__(256)
void attn_kernel(const float* __restrict__ W3e,
                 const float* __restrict__ W3m,
                 const float* __restrict__ W3c,
                 const float* __restrict__ b3e,
                 const float* __restrict__ b3m,
                 const float* __restrict__ b3c,
                 float* __restrict__ out)
{
    const int b    = blockIdx.x;
    const int pair = blockIdx.y;
    const int t    = threadIdx.x;

    __shared__ float2  sa[MDIM];       // a-side, scaled by LOG2E
    __shared__ float2  sb[MDIM];       // b-side, unscaled
    __shared__ float   xbuf[256 * 17]; // col-transpose buffer (17-pad)
    __shared__ float   red[8];
    __shared__ __half2 pax[128], pay[128], pbx[128], pby[128], prinv[128];
    __shared__ int     sfl[2];         // [0]=slast [1]=szero

    const int ai = (pair == 2) ? 1 : 0;          // e,e,m
    const int bi = (pair == 0) ? 1 : 2;          // m,c,c

    {
        const float* Pa = &g_P[ai][b][0];
        float px = Pa[t], py = Pa[MDIM + t];
        float inv = rsqrtf(px * px + py * py) * LOG2E;
        sa[t] = make_float2(px * inv, py * inv);

        const float* Pb = &g_P[bi][b][0];
        px = Pb[t]; py = Pb[MDIM + t];
        inv = rsqrtf(px * px + py * py);
        sb[t] = make_float2(px * inv, py * inv);
    }
    __syncthreads();

    const __half2 hz = __float2half2_rn(0.f);

    if (pair < 2) {
        const int ti = t >> 4;        // row group
        const int tj = t & 15;        // col group

        __half2 bx2[8], by2[8];
#pragma unroll
        for (int k = 0; k < 8; ++k) {
            float2 b0 = sb[tj * 16 + 2 * k];
            float2 b1 = sb[tj * 16 + 2 * k + 1];
            bx2[k] = __floats2half2_rn(b0.x, b1.x);
            by2[k] = __floats2half2_rn(b0.y, b1.y);
        }

        __half2 cd2[8], cn02[8], cn12[8];
#pragma unroll
        for (int k = 0; k < 8; ++k) { cd2[k] = hz; cn02[k] = hz; cn12[k] = hz; }

        float rowd = 0.f, rown0 = 0.f, rown1 = 0.f;

#pragma unroll
        for (int ri = 0; ri < 16; ++ri) {
            const float2 av = sa[ti * 16 + ri];
            const __half2 ax2 = __float2half2_rn(av.x);
            const __half2 ay2 = __float2half2_rn(av.y);
            __half2 rd2 = hz, rn02 = hz, rn12 = hz;
#pragma unroll
            for (int k = 0; k < 8; ++k) {
                const __half2 d2 = __hfma2(ay2, by2[k], __hmul2(ax2, bx2[k]));
                const __half2 X2 = h2ex2(d2);
                cd2[k]  = __hadd2(cd2[k], X2);
                cn02[k] = __hfma2(ax2, X2, cn02[k]);
                cn12[k] = __hfma2(ay2, X2, cn12[k]);
                rd2  = __hadd2(rd2, X2);
                rn02 = __hfma2(bx2[k], X2, rn02);
                rn12 = __hfma2(by2[k], X2, rn12);
            }
            float2 f0 = __half22float2(rd2);
            float2 f1 = __half22float2(rn02);
            float2 f2 = __half22float2(rn12);
            float rd = f0.x + f0.y, rn0 = f1.x + f1.y, rn1 = f2.x + f2.y;
#pragma unroll
            for (int o = 1; o < 16; o <<= 1) {
                rd  += __shfl_xor_sync(0xffffffffu, rd,  o);
                rn0 += __shfl_xor_sync(0xffffffffu, rn0, o);
                rn1 += __shfl_xor_sync(0xffffffffu, rn1, o);
            }
            if (ri == tj) { rowd = rd; rown0 = rn0; rown1 = rn1; }
        }

        float cd[16], cn0[16], cn1[16];
#pragma unroll
        for (int k = 0; k < 8; ++k) {
            float2 f;
            f = __half22float2(cd2[k]);  cd[2*k] = f.x;  cd[2*k+1] = f.y;
            f = __half22float2(cn02[k]); cn0[2*k] = f.x; cn0[2*k+1] = f.y;
            f = __half22float2(cn12[k]); cn1[2*k] = f.x; cn1[2*k+1] = f.y;
        }

        // ---- Direction B output (softmax over cols, weights=b): row = t
        {
            const float* WB = (pair == 0) ? W3m : W3c;
            float v = (rown0 * WB[t] + rown1 * WB[MDIM + t]) / rowd;
            v = block_reduce_sum(v, red);
            if (t == 0) {
                if (pair == 0) g_partial[1][0][b] = v;
                else           g_partial[2][0][b] = v;
            }
        }

        // ---- Direction A output (softmax over rows, weights=a): col = t
        float d = 0.f, n0 = 0.f, n1 = 0.f;
#pragma unroll 1
        for (int ph = 0; ph < 3; ++ph) {
            __syncthreads();
#pragma unroll
            for (int jl = 0; jl < 16; ++jl)
                xbuf[t * 17 + jl] = (ph == 0) ? cd[jl] : (ph == 1 ? cn0[jl] : cn1[jl]);
            __syncthreads();
            float s = 0.f;
#pragma unroll
            for (int tp = 0; tp < 16; ++tp)
                s += xbuf[(tp * 16 + (t >> 4)) * 17 + (t & 15)];
            if (ph == 0) d = s; else if (ph == 1) n0 = s; else n1 = s;
        }
        {
            const float* WA = W3e + (pair == 0 ? 0 : 512);
            float v = LN2 * (n0 * WA[t] + n1 * WA[MDIM + t]) / d;
            v = block_reduce_sum(v, red);
            if (t == 0) g_partial[0][pair][b] = v;
        }
    } else {
        // pack half2 operand arrays (threads 0..127)
        if (t < 128) {
            float2 a0 = sa[2 * t], a1 = sa[2 * t + 1];
            pax[t] = __floats2half2_rn(a0.x, a1.x);
            pay[t] = __floats2half2_rn(a0.y, a1.y);
            float2 b0 = sb[2 * t], b1 = sb[2 * t + 1];
            pbx[t] = __floats2half2_rn(b0.x, b1.x);
            pby[t] = __floats2half2_rn(b0.y, b1.y);
        }
        __syncthreads();

        // ---- Pass 1: thread t = m-index. att_cm output + rinv
        {
            const __half2 ax2 = __float2half2_rn(sa[t].x);
            const __half2 ay2 = __float2half2_rn(sa[t].y);
            float d = 0.f, n0 = 0.f, n1 = 0.f;
#pragma unroll 2
            for (int ko = 0; ko < 16; ++ko) {
                __half2 d2 = hz, n02 = hz, n12 = hz;
#pragma unroll
                for (int ki = 0; ki < 8; ++ki) {
                    const int k = ko * 8 + ki;
                    const __half2 e2 = __hfma2(ay2, pby[k], __hmul2(ax2, pbx[k]));
                    const __half2 X2 = h2ex2(e2);
                    d2  = __hadd2(d2, X2);
                    n02 = __hfma2(pbx[k], X2, n02);
                    n12 = __hfma2(pby[k], X2, n12);
                }
                float2 f;
                f = __half22float2(d2);  d  += f.x + f.y;
                f = __half22float2(n02); n0 += f.x + f.y;
                f = __half22float2(n12); n1 += f.x + f.y;
            }
            const float id = 1.0f / d;
            reinterpret_cast<__half*>(prinv)[t] = __float2half(id);
            float v = (n0 * W3c[512 + t] + n1 * W3c[768 + t]) * id;
            v = block_reduce_sum(v, red);     // internal syncs publish prinv
            if (t == 0) g_partial[2][1][b] = v;
        }
        // ---- Pass 2: thread t = c-index. att_mc (weights = a, *LN2)
        {
            const __half2 cx2 = __float2half2_rn(sb[t].x);
            const __half2 cy2 = __float2half2_rn(sb[t].y);
            float n0 = 0.f, n1 = 0.f;
#pragma unroll 2
            for (int ko = 0; ko < 16; ++ko) {
                __half2 n02 = hz, n12 = hz;
#pragma unroll
                for (int ki = 0; ki < 8; ++ki) {
                    const int k = ko * 8 + ki;
                    const __half2 e2 = __hfma2(pay[k], cy2, __hmul2(pax[k], cx2));
                    const __half2 X2 = __hmul2(h2ex2(e2), prinv[k]);
                    n02 = __hfma2(pax[k], X2, n02);
                    n12 = __hfma2(pay[k], X2, n12);
                }
                float2 f;
                f = __half22float2(n02); n0 += f.x + f.y;
                f = __half22float2(n12); n1 += f.x + f.y;
            }
            float v = LN2 * (n0 * W3m[512 + t] + n1 * W3m[768 + t]);
            v = block_reduce_sum(v, red);
            if (t == 0) g_partial[1][1][b] = v;
        }
    }

    // ---- per-batch g_P re-zero (for next graph replay) + final head
    __syncthreads();            // all reads of g_P / writes of partials done
    __threadfence();
    if (t == 0) {
        sfl[1] = (atomicAdd(&g_bcnt[b], 1) == 2) ? 1 : 0;
        int tk = atomicAdd(&g_done, 1);
        sfl[0] = (tk == NUNITS - 1) ? 1 : 0;
    }
    __syncthreads();
    if (sfl[1]) {
        // all 3 units of batch b have finished their reads of g_P[*][b][*]
#pragma unroll
        for (int md = 0; md < 3; ++md) {
            float2* p = reinterpret_cast<float2*>(&g_P[md][b][0]);
            p[t] = make_float2(0.f, 0.f);
        }
        if (t == 0) g_bcnt[b] = 0;
    }
    if (sfl[0]) {
        __threadfence();
#pragma unroll
        for (int q = 0; q < 2; ++q) {
            const int bb = t + q * 256;
            const float xe = g_partial[0][0][bb] + g_partial[0][1][bb] + b3e[0];
            const float xm = g_partial[1][0][bb] + g_partial[1][1][bb] + b3m[0];
            const float xc = g_partial[2][0][bb] + g_partial[2][1][bb] + b3c[0];
            out[bb]             = 1.0f / (1.0f + expf(-xe));
            out[BATCH + bb]     = 1.0f / (1.0f + expf(-xm));
            out[2 * BATCH + bb] = 1.0f / (1.0f + expf(-xc));
        }
        if (t == 0) g_done = 0;   // reset for next graph replay
    }
}

// ---------------------------------------------------------------------------
// Launch
// ---------------------------------------------------------------------------
extern "C" void kernel_launch(void* const* d_in, const int* in_sizes, int n_in,
                              void* d_out, int out_size)
{
    const float* expr = (const float*)d_in[0];
    const float* mut  = (const float*)d_in[1];
    const float* cna  = (const float*)d_in[2];
    const float* Wex  = (const float*)d_in[3];
    const float* Wey  = (const float*)d_in[4];
    const float* Wmx  = (const float*)d_in[5];
    const float* Wmy  = (const float*)d_in[6];
    const float* Wcx  = (const float*)d_in[7];
    const float* Wcy  = (const float*)d_in[8];
    const float* W3e  = (const float*)d_in[9];
    const float* b3e  = (const float*)d_in[10];
    const float* W3m  = (const float*)d_in[11];
    const float* b3m  = (const float*)d_in[12];
    const float* W3c  = (const float*)d_in[13];
    const float* b3c  = (const float*)d_in[14];

    const int K1 = in_sizes[0] / BATCH;   // 20000
    const int K2 = in_sizes[1] / BATCH;   // 15000
    const int K3 = in_sizes[2] / BATCH;   // 20000

    const int SMEM = STG * (AST + BST) * 4;   // 3 * 48KB = 147456 B
    static bool attr_set = false;
    if (!attr_set) {
        cudaFuncSetAttribute(gemm_mma, cudaFuncAttributeMaxDynamicSharedMemorySize, SMEM);
        attr_set = true;
    }

    gemm_mma<<<dim3(4, 2, SPLIT), NTHR, SMEM>>>(
        expr, mut, cna, Wex, Wey, Wmx, Wmy, Wcx, Wcy, K1, K2, K3);

    attn_kernel<<<dim3(BATCH, 3), 256>>>(W3e, W3m, W3c, b3e, b3m, b3c,
                                         (float*)d_out);
}

// round 16
// speedup vs baseline: 1.1771x; 1.0021x over previous
#include <cuda_runtime.h>
#include <cuda_bf16.h>
#include <cuda_fp16.h>
#include <math.h>
#include <stdint.h>

#define BATCH 512
#define MDIM  256
#define NCOLS 512

#define BM 128
#define BN 256
#define BK 32           // two 16-wide k-groups per barrier interval
#define STG 3
#define SPLIT 18        // split-K CTAs per modality -> 4*2*18 = 144 CTAs
#define NTHR 256        // 8 warps: 2(m) x 4(n), warp tile 64x64
#define NUNITS (3 * BATCH)

#define AST16 (BM * 16)           // A sub-tile (one k-group): 2048 floats
#define BST16 (BN * 16)           // B sub-tile: 4096 floats
#define AST   (2 * AST16)         // per stage
#define BST   (2 * BST16)

#define LOG2E 1.4426950408889634f
#define LN2   0.6931471805599453f

__device__ float g_P[3][BATCH][NCOLS];      // projections (atomic-accumulated; zero-init at load)
__device__ float g_partial[3][2][BATCH];    // per-head partial dots
__device__ int   g_done;                    // attn block completion counter
__device__ int   g_bcnt[BATCH];             // per-batch attn completion counters

// ---------------------------------------------------------------------------
// helpers
// ---------------------------------------------------------------------------
__device__ __forceinline__ uint32_t smem_u32(const void* p) {
    uint32_t a;
    asm("{ .reg .u64 t; cvta.to.shared.u64 t, %1; cvt.u32.u64 %0, t; }" : "=r"(a) : "l"(p));
    return a;
}
__device__ __forceinline__ void cpa16(float* dst, const float* src, int nb) {
    asm volatile("cp.async.cg.shared.global [%0], [%1], 16, %2;"
                 :: "r"(smem_u32(dst)), "l"(src), "r"(nb) : "memory");
}
// pack two f32 into f16x2: low half = lo (lower k index), high half = hi
__device__ __forceinline__ uint32_t pk(uint32_t lo, uint32_t hi) {
    uint32_t d;
    asm("cvt.rn.f16x2.f32 %0, %1, %2;"
        : "=r"(d) : "f"(__uint_as_float(hi)), "f"(__uint_as_float(lo)));
    return d;
}
__device__ __forceinline__ void mma_f16(float* d, uint32_t a0, uint32_t a1,
                                        uint32_t a2, uint32_t a3,
                                        uint32_t b0, uint32_t b1) {
    asm volatile(
        "mma.sync.aligned.m16n8k16.row.col.f32.f16.f16.f32 "
        "{%0,%1,%2,%3}, {%4,%5,%6,%7}, {%8,%9}, {%0,%1,%2,%3};"
        : "+f"(d[0]), "+f"(d[1]), "+f"(d[2]), "+f"(d[3])
        : "r"(a0), "r"(a1), "r"(a2), "r"(a3), "r"(b0), "r"(b1));
}
__device__ __forceinline__ float ex2f(float x) {
    float y; asm("ex2.approx.f32 %0, %1;" : "=f"(y) : "f"(x)); return y;
}
__device__ __forceinline__ __half2 h2ex2(__half2 x) {
    uint32_t xi = *reinterpret_cast<uint32_t*>(&x), yi;
    asm("ex2.approx.f16x2 %0, %1;" : "=r"(yi) : "r"(xi));
    return *reinterpret_cast<__half2*>(&yi);
}

// ---------------------------------------------------------------------------
// stage loader: A tile 128x32, B tile 256x32, two 16-wide k-group sub-tiles
// ---------------------------------------------------------------------------
__device__ __forceinline__ void load_stage(
    const float* __restrict__ A, const float* __restrict__ W,
    int K, int mt, int kt, float* As, float* Bs, int tid)
{
#pragma unroll
    for (int h = 0; h < 4; ++h) {                 // A: 1024 16B chunks
        const int ch  = tid + h * NTHR;
        const int row = ch >> 3, kc = ch & 7;
        const int g   = kc >> 2, kcc = kc & 3;
        const int k   = kt + kc * 4;
        int nb = (K - k) * 4; nb = nb < 0 ? 0 : (nb > 16 ? 16 : nb);
        const int ks = (k < K) ? k : 0;
        cpa16(As + g * AST16 + row * 16 + kcc * 4,
              A + (size_t)(mt * BM + row) * K + ks, nb);
    }
#pragma unroll
    for (int h = 0; h < 8; ++h) {                 // B: 2048 chunks
        const int ch  = tid + h * NTHR;
        const int row = ch >> 3, kc = ch & 7;
        const int g   = kc >> 2, kcc = kc & 3;
        const int k   = kt + kc * 4;
        int nb = (K - k) * 4; nb = nb < 0 ? 0 : (nb > 16 ? 16 : nb);
        const int ks = (k < K) ? k : 0;
        cpa16(Bs + g * BST16 + row * 16 + kcc * 4,
              W + (size_t)row * K + ks, nb);
    }
}

// ---------------------------------------------------------------------------
// fp16 mma.sync GEMM (m16n8k16, fp32 accum), 128x256 CTA tile, BK=32
// ---------------------------------------------------------------------------
__global__ __launch_bounds__(NTHR, 1)
void gemm_mma(const float* __restrict__ e, const float* __restrict__ m,
              const float* __restrict__ c,
              const float* __restrict__ Wex, const float* __restrict__ Wey,
              const float* __restrict__ Wmx, const float* __restrict__ Wmy,
              const float* __restrict__ Wcx, const float* __restrict__ Wcy,
              int K0, int K1, int K2)
{
    const int mt = blockIdx.x;
    const int nt = blockIdx.y;
    const int sp = blockIdx.z;

    extern __shared__ float smf[];
    float* As = smf;                          // [STG][AST]
    float* Bs = smf + STG * AST;              // [STG][BST]

    const int tid  = threadIdx.x;
    const int lane = tid & 31;
    const int wid  = tid >> 5;
    const int wm   = (wid & 1) * 64;          // warp grid 2(m) x 4(n)
    const int wn   = (wid >> 1) * 64;
    const int r    = lane >> 2;
    const int cq   = lane & 3;

#pragma unroll 1
    for (int mod = 0; mod < 3; ++mod) {
        const float* A = (mod == 0) ? e : (mod == 1 ? m : c);
        const float* W;
        if (mod == 0) W = nt ? Wey : Wex;
        else if (mod == 1) W = nt ? Wmy : Wmx;
        else W = nt ? Wcy : Wcx;
        const int K = (mod == 0) ? K0 : (mod == 1 ? K1 : K2);

        const int nk  = (K + BK - 1) / BK;
        const int per = (nk + SPLIT - 1) / SPLIT;
        const int i0  = sp * per;
        const int i1  = min(nk, i0 + per);
        const int n   = i1 - i0;
        if (n <= 0) { __syncthreads(); continue; }

        float acc[4][8][4];
#pragma unroll
        for (int a = 0; a < 4; ++a)
#pragma unroll
            for (int b = 0; b < 8; ++b)
#pragma unroll
                for (int q = 0; q < 4; ++q) acc[a][b][q] = 0.f;

#pragma unroll
        for (int s = 0; s < STG - 1; ++s) {
            if (s < n) load_stage(A, W, K, mt, (i0 + s) * BK,
                                  As + s * AST, Bs + s * BST, tid);
            asm volatile("cp.async.commit_group;" ::: "memory");
        }

#pragma unroll 1
        for (int it = 0; it < n; ++it) {
            asm volatile("cp.async.wait_group %0;" :: "n"(STG - 2) : "memory");
            __syncthreads();

            if (it + STG - 1 < n) {
                const int ws = (it + STG - 1) % STG;
                load_stage(A, W, K, mt, (i0 + it + STG - 1) * BK,
                           As + ws * AST, Bs + ws * BST, tid);
            }
            asm volatile("cp.async.commit_group;" ::: "memory");

            const int s = it % STG;

#pragma unroll
            for (int g = 0; g < 2; ++g) {
                const float* Ab = As + s * AST + g * AST16;
                const float* Bb = Bs + s * BST + g * BST16;

                uint4 alo[4], ahi[4], bv[8];
#pragma unroll
                for (int mi = 0; mi < 4; ++mi) {
                    const float* ap = Ab + (wm + mi * 16 + r) * 16 + cq * 4;
                    alo[mi] = *reinterpret_cast<const uint4*>(ap);
                    ahi[mi] = *reinterpret_cast<const uint4*>(ap + 8 * 16);
                }
#pragma unroll
                for (int ni = 0; ni < 8; ++ni) {
                    const float* bp = Bb + (wn + ni * 8 + r) * 16 + cq * 4;
                    bv[ni] = *reinterpret_cast<const uint4*>(bp);
                }

                uint32_t af[4][4], bf[8][2];
#pragma unroll
                for (int mi = 0; mi < 4; ++mi) {
                    af[mi][0] = pk(alo[mi].x, alo[mi].y);
                    af[mi][1] = pk(ahi[mi].x, ahi[mi].y);
                    af[mi][2] = pk(alo[mi].z, alo[mi].w);
                    af[mi][3] = pk(ahi[mi].z, ahi[mi].w);
                }
#pragma unroll
                for (int ni = 0; ni < 8; ++ni) {
                    bf[ni][0] = pk(bv[ni].x, bv[ni].y);
                    bf[ni][1] = pk(bv[ni].z, bv[ni].w);
                }

#pragma unroll
                for (int mi = 0; mi < 4; ++mi)
#pragma unroll
                    for (int ni = 0; ni < 8; ++ni)
                        mma_f16(acc[mi][ni], af[mi][0], af[mi][1], af[mi][2], af[mi][3],
                                bf[ni][0], bf[ni][1]);
            }
        }

        asm volatile("cp.async.wait_group 0;" ::: "memory");
        __syncthreads();

        float* Cb = &g_P[mod][0][0];
#pragma unroll
        for (int mi = 0; mi < 4; ++mi) {
            const int row = mt * BM + wm + mi * 16 + r;
#pragma unroll
            for (int ni = 0; ni < 8; ++ni) {
                const int col = nt * BN + wn + ni * 8 + cq * 2;
                float* p0 = Cb + (size_t)row * NCOLS + col;
                float* p1 = p0 + 8 * NCOLS;
                asm volatile("red.global.add.v2.f32 [%0], {%1, %2};"
                             :: "l"(p0), "f"(acc[mi][ni][0]), "f"(acc[mi][ni][1]) : "memory");
                asm volatile("red.global.add.v2.f32 [%0], {%1, %2};"
                             :: "l"(p1), "f"(acc[mi][ni][2]), "f"(acc[mi][ni][3]) : "memory");
            }
        }
    }
}

// ---------------------------------------------------------------------------
// block reduce (value valid on thread 0)
// ---------------------------------------------------------------------------
__device__ __forceinline__ float block_reduce_sum(float v, float* red) {
#pragma unroll
    for (int o = 16; o; o >>= 1) v += __shfl_xor_sync(0xffffffffu, v, o);
    const int t = threadIdx.x;
    __syncthreads();
    if ((t & 31) == 0) red[t >> 5] = v;
    __syncthreads();
    if (t == 0) {
        float s = 0.f;
#pragma unroll
        for (int i = 0; i < 8; ++i) s += red[i];
        v = s;
    }
    return v;
}

// ---------------------------------------------------------------------------
// Fused attention (R14 math). Register diet: the fp16 column accumulators
// are unpacked to fp32 INSIDE the transpose-phase loop (no fp32[16] arrays
// live across phases) and __launch_bounds__(256, 4) pins regs <= 64 so 4
// CTAs/SM fit (was 3 at 75 regs, occ 34% -> fma pipe half idle).
// ---------------------------------------------------------------------------
__global__ __launch_bounds__(256, 4)
void attn_kernel(const float* __restrict__ W3e,
                 const float* __restrict__ W3m,
                 const float* __restrict__ W3c,
                 const float* __restrict__ b3e,
                 const float* __restrict__ b3m,
                 const float* __restrict__ b3c,
                 float* __restrict__ out)
{
    const int b    = blockIdx.x;
    const int pair = blockIdx.y;
    const int t    = threadIdx.x;

    __shared__ float2  sa[MDIM];       // a-side, scaled by LOG2E
    __shared__ float2  sb[MDIM];       // b-side, unscaled
    __shared__ float   xbuf[256 * 17]; // col-transpose buffer (17-pad)
    __shared__ float   red[8];
    __shared__ __half2 pax[128], pay[128], pbx[128], pby[128], prinv[128];
    __shared__ int     sfl[2];         // [0]=slast [1]=szero

    const int ai = (pair == 2) ? 1 : 0;          // e,e,m
    const int bi = (pair == 0) ? 1 : 2;          // m,c,c

    {
        const float* Pa = &g_P[ai][b][0];
        float px = Pa[t], py = Pa[MDIM + t];
        float inv = rsqrtf(px * px + py * py) * LOG2E;
        sa[t] = make_float2(px * inv, py * inv);

        const float* Pb = &g_P[bi][b][0];
        px = Pb[t]; py = Pb[MDIM + t];
        inv = rsqrtf(px * px + py * py);
        sb[t] = make_float2(px * inv, py * inv);
    }
    __syncthreads();

    const __half2 hz = __float2half2_rn(0.f);

    if (pair < 2) {
        const int ti = t >> 4;        // row group
        const int tj = t & 15;        // col group

        __half2 bx2[8], by2[8];
#pragma unroll
        for (int k = 0; k < 8; ++k) {
            float2 b0 = sb[tj * 16 + 2 * k];
            float2 b1 = sb[tj * 16 + 2 * k + 1];
            bx2[k] = __floats2half2_rn(b0.x, b1.x);
            by2[k] = __floats2half2_rn(b0.y, b1.y);
        }

        __half2 cd2[8], cn02[8], cn12[8];
#pragma unroll
        for (int k = 0; k < 8; ++k) { cd2[k] = hz; cn02[k] = hz; cn12[k] = hz; }

        float rowd = 0.f, rown0 = 0.f, rown1 = 0.f;

#pragma unroll
        for (int ri = 0; ri < 16; ++ri) {
            const float2 av = sa[ti * 16 + ri];
            const __half2 ax2 = __float2half2_rn(av.x);
            const __half2 ay2 = __float2half2_rn(av.y);
            __half2 rd2 = hz, rn02 = hz, rn12 = hz;
#pragma unroll
            for (int k = 0; k < 8; ++k) {
                const __half2 d2 = __hfma2(ay2, by2[k], __hmul2(ax2, bx2[k]));
                const __half2 X2 = h2ex2(d2);
                cd2[k]  = __hadd2(cd2[k], X2);
                cn02[k] = __hfma2(ax2, X2, cn02[k]);
                cn12[k] = __hfma2(ay2, X2, cn12[k]);
                rd2  = __hadd2(rd2, X2);
                rn02 = __hfma2(bx2[k], X2, rn02);
                rn12 = __hfma2(by2[k], X2, rn12);
            }
            float2 f0 = __half22float2(rd2);
            float2 f1 = __half22float2(rn02);
            float2 f2 = __half22float2(rn12);
            float rd = f0.x + f0.y, rn0 = f1.x + f1.y, rn1 = f2.x + f2.y;
#pragma unroll
            for (int o = 1; o < 16; o <<= 1) {
                rd  += __shfl_xor_sync(0xffffffffu, rd,  o);
                rn0 += __shfl_xor_sync(0xffffffffu, rn0, o);
                rn1 += __shfl_xor_sync(0xffffffffu, rn1, o);
            }
            if (ri == tj) { rowd = rd; rown0 = rn0; rown1 = rn1; }
        }

        // ---- Direction B output (softmax over cols, weights=b): row = t
        {
            const float* WB = (pair == 0) ? W3m : W3c;
            float v = (rown0 * WB[t] + rown1 * WB[MDIM + t]) / rowd;
            v = block_reduce_sum(v, red);
            if (t == 0) {
                if (pair == 0) g_partial[1][0][b] = v;
                else           g_partial[2][0][b] = v;
            }
        }

        // ---- Direction A output (softmax over rows, weights=a): col = t
        // unpack the half2 accumulators inside each phase (no fp32[16] arrays)
        float d = 0.f, n0 = 0.f, n1 = 0.f;
#pragma unroll 1
        for (int ph = 0; ph < 3; ++ph) {
            __syncthreads();
#pragma unroll
            for (int k = 0; k < 8; ++k) {
                const __half2 src = (ph == 0) ? cd2[k] : (ph == 1 ? cn02[k] : cn12[k]);
                const float2 f = __half22float2(src);
                xbuf[t * 17 + 2 * k]     = f.x;
                xbuf[t * 17 + 2 * k + 1] = f.y;
            }
            __syncthreads();
            float s = 0.f;
#pragma unroll
            for (int tp = 0; tp < 16; ++tp)
                s += xbuf[(tp * 16 + (t >> 4)) * 17 + (t & 15)];
            if (ph == 0) d = s; else if (ph == 1) n0 = s; else n1 = s;
        }
        {
            const float* WA = W3e + (pair == 0 ? 0 : 512);
            float v = LN2 * (n0 * WA[t] + n1 * WA[MDIM + t]) / d;
            v = block_reduce_sum(v, red);
            if (t == 0) g_partial[0][pair][b] = v;
        }
    } else {
        // pack half2 operand arrays (threads 0..127)
        if (t < 128) {
            float2 a0 = sa[2 * t], a1 = sa[2 * t + 1];
            pax[t] = __floats2half2_rn(a0.x, a1.x);
            pay[t] = __floats2half2_rn(a0.y, a1.y);
            float2 b0 = sb[2 * t], b1 = sb[2 * t + 1];
            pbx[t] = __floats2half2_rn(b0.x, b1.x);
            pby[t] = __floats2half2_rn(b0.y, b1.y);
        }
        __syncthreads();

        // ---- Pass 1: thread t = m-index. att_cm output + rinv
        {
            const __half2 ax2 = __float2half2_rn(sa[t].x);
            const __half2 ay2 = __float2half2_rn(sa[t].y);
            float d = 0.f, n0 = 0.f, n1 = 0.f;
#pragma unroll 2
            for (int ko = 0; ko < 16; ++ko) {
                __half2 d2 = hz, n02 = hz, n12 = hz;
#pragma unroll
                for (int ki = 0; ki < 8; ++ki) {
                    const int k = ko * 8 + ki;
                    const __half2 e2 = __hfma2(ay2, pby[k], __hmul2(ax2, pbx[k]));
                    const __half2 X2 = h2ex2(e2);
                    d2  = __hadd2(d2, X2);
                    n02 = __hfma2(pbx[k], X2, n02);
                    n12 = __hfma2(pby[k], X2, n12);
                }
                float2 f;
                f = __half22float2(d2);  d  += f.x + f.y;
                f = __half22float2(n02); n0 += f.x + f.y;
                f = __half22float2(n12); n1 += f.x + f.y;
            }
            const float id = 1.0f / d;
            reinterpret_cast<__half*>(prinv)[t] = __float2half(id);
            float v = (n0 * W3c[512 + t] + n1 * W3c[768 + t]) * id;
            v = block_reduce_sum(v, red);     // internal syncs publish prinv
            if (t == 0) g_partial[2][1][b] = v;
        }
        // ---- Pass 2: thread t = c-index. att_mc (weights = a, *LN2)
        {
            const __half2 cx2 = __float2half2_rn(sb[t].x);
            const __half2 cy2 = __float2half2_rn(sb[t].y);
            float n0 = 0.f, n1 = 0.f;
#pragma unroll 2
            for (int ko = 0; ko < 16; ++ko) {
                __half2 n02 = hz, n12 = hz;
#pragma unroll
                for (int ki = 0; ki < 8; ++ki) {
                    const int k = ko * 8 + ki;
                    const __half2 e2 = __hfma2(pay[k], cy2, __hmul2(pax[k], cx2));
                    const __half2 X2 = __hmul2(h2ex2(e2), prinv[k]);
                    n02 = __hfma2(pax[k], X2, n02);
                    n12 = __hfma2(pay[k], X2, n12);
                }
                float2 f;
                f = __half22float2(n02); n0 += f.x + f.y;
                f = __half22float2(n12); n1 += f.x + f.y;
            }
            float v = LN2 * (n0 * W3m[512 + t] + n1 * W3m[768 + t]);
            v = block_reduce_sum(v, red);
            if (t == 0) g_partial[1][1][b] = v;
        }
    }

    // ---- per-batch g_P re-zero (for next graph replay) + final head
    __syncthreads();            // all reads of g_P / writes of partials done
    __threadfence();
    if (t == 0) {
        sfl[1] = (atomicAdd(&g_bcnt[b], 1) == 2) ? 1 : 0;
        int tk = atomicAdd(&g_done, 1);
        sfl[0] = (tk == NUNITS - 1) ? 1 : 0;
    }
    __syncthreads();
    if (sfl[1]) {
        // all 3 units of batch b have finished their reads of g_P[*][b][*]
#pragma unroll
        for (int md = 0; md < 3; ++md) {
            float2* p = reinterpret_cast<float2*>(&g_P[md][b][0]);
            p[t] = make_float2(0.f, 0.f);
        }
        if (t == 0) g_bcnt[b] = 0;
    }
    if (sfl[0]) {
        __threadfence();
#pragma unroll
        for (int q = 0; q < 2; ++q) {
            const int bb = t + q * 256;
            const float xe = g_partial[0][0][bb] + g_partial[0][1][bb] + b3e[0];
            const float xm = g_partial[1][0][bb] + g_partial[1][1][bb] + b3m[0];
            const float xc = g_partial[2][0][bb] + g_partial[2][1][bb] + b3c[0];
            out[bb]             = 1.0f / (1.0f + expf(-xe));
            out[BATCH + bb]     = 1.0f / (1.0f + expf(-xm));
            out[2 * BATCH + bb] = 1.0f / (1.0f + expf(-xc));
        }
        if (t == 0) g_done = 0;   // reset for next graph replay
    }
}

// ---------------------------------------------------------------------------
// Launch
// ---------------------------------------------------------------------------
extern "C" void kernel_launch(void* const* d_in, const int* in_sizes, int n_in,
                              void* d_out, int out_size)
{
    const float* expr = (const float*)d_in[0];
    const float* mut  = (const float*)d_in[1];
    const float* cna  = (const float*)d_in[2];
    const float* Wex  = (const float*)d_in[3];
    const float* Wey  = (const float*)d_in[4];
    const float* Wmx  = (const float*)d_in[5];
    const float* Wmy  = (const float*)d_in[6];
    const float* Wcx  = (const float*)d_in[7];
    const float* Wcy  = (const float*)d_in[8];
    const float* W3e  = (const float*)d_in[9];
    const float* b3e  = (const float*)d_in[10];
    const float* W3m  = (const float*)d_in[11];
    const float* b3m  = (const float*)d_in[12];
    const float* W3c  = (const float*)d_in[13];
    const float* b3c  = (const float*)d_in[14];

    const int K1 = in_sizes[0] / BATCH;   // 20000
    const int K2 = in_sizes[1] / BATCH;   // 15000
    const int K3 = in_sizes[2] / BATCH;   // 20000

    const int SMEM = STG * (AST + BST) * 4;   // 3 * 48KB = 147456 B
    static bool attr_set = false;
    if (!attr_set) {
        cudaFuncSetAttribute(gemm_mma, cudaFuncAttributeMaxDynamicSharedMemorySize, SMEM);
        attr_set = true;
    }

    gemm_mma<<<dim3(4, 2, SPLIT), NTHR, SMEM>>>(
        expr, mut, cna, Wex, Wey, Wmx, Wmy, Wcx, Wcy, K1, K2, K3);

    attn_kernel<<<dim3(BATCH, 3), 256>>>(W3e, W3m, W3c, b3e, b3m, b3c,
                                         (float*)d_out);
}

// round 17
// speedup vs baseline: 1.1934x; 1.0138x over previous
#include <cuda_runtime.h>
#include <cuda_bf16.h>
#include <cuda_fp16.h>
#include <math.h>
#include <stdint.h>

#define BATCH 512
#define MDIM  256
#define NCOLS 512

#define BM 128
#define BN 256
#define BK 32           // two 16-wide k-groups per barrier interval
#define STG 4           // 4 stage slots: stage it+1 resident during iter it
#define SPLIT 18        // split-K CTAs per modality -> 4*2*18 = 144 CTAs
#define NTHR 256        // 8 warps: 2(m) x 4(n), warp tile 64x64
#define NUNITS (3 * BATCH)

#define AST16 (BM * 16)           // A sub-tile (one k-group): 2048 floats
#define BST16 (BN * 16)           // B sub-tile: 4096 floats
#define AST   (2 * AST16)         // per stage
#define BST   (2 * BST16)

#define LOG2E 1.4426950408889634f
#define LN2   0.6931471805599453f

__device__ float g_P[3][BATCH][NCOLS];      // projections (atomic-accumulated; zero-init at load)
__device__ float g_partial[3][2][BATCH];    // per-head partial dots
__device__ int   g_done;                    // attn block completion counter
__device__ int   g_bcnt[BATCH];             // per-batch attn completion counters

// ---------------------------------------------------------------------------
// helpers
// ---------------------------------------------------------------------------
__device__ __forceinline__ uint32_t smem_u32(const void* p) {
    uint32_t a;
    asm("{ .reg .u64 t; cvta.to.shared.u64 t, %1; cvt.u32.u64 %0, t; }" : "=r"(a) : "l"(p));
    return a;
}
__device__ __forceinline__ void cpa16(float* dst, const float* src, int nb) {
    asm volatile("cp.async.cg.shared.global [%0], [%1], 16, %2;"
                 :: "r"(smem_u32(dst)), "l"(src), "r"(nb) : "memory");
}
// pack two f32 into f16x2: low half = lo (lower k index), high half = hi
__device__ __forceinline__ uint32_t pk(uint32_t lo, uint32_t hi) {
    uint32_t d;
    asm("cvt.rn.f16x2.f32 %0, %1, %2;"
        : "=r"(d) : "f"(__uint_as_float(hi)), "f"(__uint_as_float(lo)));
    return d;
}
__device__ __forceinline__ void mma_f16(float* d, uint32_t a0, uint32_t a1,
                                        uint32_t a2, uint32_t a3,
                                        uint32_t b0, uint32_t b1) {
    asm volatile(
        "mma.sync.aligned.m16n8k16.row.col.f32.f16.f16.f32 "
        "{%0,%1,%2,%3}, {%4,%5,%6,%7}, {%8,%9}, {%0,%1,%2,%3};"
        : "+f"(d[0]), "+f"(d[1]), "+f"(d[2]), "+f"(d[3])
        : "r"(a0), "r"(a1), "r"(a2), "r"(a3), "r"(b0), "r"(b1));
}
__device__ __forceinline__ float ex2f(float x) {
    float y; asm("ex2.approx.f32 %0, %1;" : "=f"(y) : "f"(x)); return y;
}
__device__ __forceinline__ __half2 h2ex2(__half2 x) {
    uint32_t xi = *reinterpret_cast<uint32_t*>(&x), yi;
    asm("ex2.approx.f16x2 %0, %1;" : "=r"(yi) : "r"(xi));
    return *reinterpret_cast<__half2*>(&yi);
}

// ---------------------------------------------------------------------------
// stage loader: A tile 128x32, B tile 256x32, two 16-wide k-group sub-tiles
// ---------------------------------------------------------------------------
__device__ __forceinline__ void load_stage(
    const float* __restrict__ A, const float* __restrict__ W,
    int K, int mt, int kt, float* As, float* Bs, int tid)
{
#pragma unroll
    for (int h = 0; h < 4; ++h) {                 // A: 1024 16B chunks
        const int ch  = tid + h * NTHR;
        const int row = ch >> 3, kc = ch & 7;
        const int g   = kc >> 2, kcc = kc & 3;
        const int k   = kt + kc * 4;
        int nb = (K - k) * 4; nb = nb < 0 ? 0 : (nb > 16 ? 16 : nb);
        const int ks = (k < K) ? k : 0;
        cpa16(As + g * AST16 + row * 16 + kcc * 4,
              A + (size_t)(mt * BM + row) * K + ks, nb);
    }
#pragma unroll
    for (int h = 0; h < 8; ++h) {                 // B: 2048 chunks
        const int ch  = tid + h * NTHR;
        const int row = ch >> 3, kc = ch & 7;
        const int g   = kc >> 2, kcc = kc & 3;
        const int k   = kt + kc * 4;
        int nb = (K - k) * 4; nb = nb < 0 ? 0 : (nb > 16 ? 16 : nb);
        const int ks = (k < K) ? k : 0;
        cpa16(Bs + g * BST16 + row * 16 + kcc * 4,
              W + (size_t)row * K + ks, nb);
    }
}

// load one k-group's fragments from smem and convert to f16x2 held regs
__device__ __forceinline__ void frag_load(
    const float* Ab, const float* Bb, int wm, int wn, int r, int cq,
    uint32_t haf[4][4], uint32_t hbf[8][2])
{
    uint4 alo[4], ahi[4], bv[8];
#pragma unroll
    for (int mi = 0; mi < 4; ++mi) {
        const float* ap = Ab + (wm + mi * 16 + r) * 16 + cq * 4;
        alo[mi] = *reinterpret_cast<const uint4*>(ap);
        ahi[mi] = *reinterpret_cast<const uint4*>(ap + 8 * 16);
    }
#pragma unroll
    for (int ni = 0; ni < 8; ++ni) {
        const float* bp = Bb + (wn + ni * 8 + r) * 16 + cq * 4;
        bv[ni] = *reinterpret_cast<const uint4*>(bp);
    }
#pragma unroll
    for (int mi = 0; mi < 4; ++mi) {
        haf[mi][0] = pk(alo[mi].x, alo[mi].y);
        haf[mi][1] = pk(ahi[mi].x, ahi[mi].y);
        haf[mi][2] = pk(alo[mi].z, alo[mi].w);
        haf[mi][3] = pk(ahi[mi].z, ahi[mi].w);
    }
#pragma unroll
    for (int ni = 0; ni < 8; ++ni) {
        hbf[ni][0] = pk(bv[ni].x, bv[ni].y);
        hbf[ni][1] = pk(bv[ni].z, bv[ni].w);
    }
}

__device__ __forceinline__ void frag_mma(
    float acc[4][8][4], const uint32_t haf[4][4], const uint32_t hbf[8][2])
{
#pragma unroll
    for (int mi = 0; mi < 4; ++mi)
#pragma unroll
        for (int ni = 0; ni < 8; ++ni)
            mma_f16(acc[mi][ni], haf[mi][0], haf[mi][1], haf[mi][2], haf[mi][3],
                    hbf[ni][0], hbf[ni][1]);
}

// ---------------------------------------------------------------------------
// fp16 mma.sync GEMM (m16n8k16, fp32 accum), 128x256 CTA tile, BK=32,
// STG=4 with a one-iteration-deep fragment pipeline: group 0 of stage it+1
// is loaded+converted into held registers during iter it (stage it+1 smem is
// guaranteed resident by wait_group(1)), so its LDS/cvt overlaps the tensor
// pipe instead of serializing after the barrier.
// ---------------------------------------------------------------------------
__global__ __launch_bounds__(NTHR, 1)
void gemm_mma(const float* __restrict__ e, const float* __restrict__ m,
              const float* __restrict__ c,
              const float* __restrict__ Wex, const float* __restrict__ Wey,
              const float* __restrict__ Wmx, const float* __restrict__ Wmy,
              const float* __restrict__ Wcx, const float* __restrict__ Wcy,
              int K0, int K1, int K2)
{
    const int mt = blockIdx.x;
    const int nt = blockIdx.y;
    const int sp = blockIdx.z;

    extern __shared__ float smf[];
    float* As = smf;                          // [STG][AST]
    float* Bs = smf + STG * AST;              // [STG][BST]

    const int tid  = threadIdx.x;
    const int lane = tid & 31;
    const int wid  = tid >> 5;
    const int wm   = (wid & 1) * 64;          // warp grid 2(m) x 4(n)
    const int wn   = (wid >> 1) * 64;
    const int r    = lane >> 2;
    const int cq   = lane & 3;

#pragma unroll 1
    for (int mod = 0; mod < 3; ++mod) {
        const float* A = (mod == 0) ? e : (mod == 1 ? m : c);
        const float* W;
        if (mod == 0) W = nt ? Wey : Wex;
        else if (mod == 1) W = nt ? Wmy : Wmx;
        else W = nt ? Wcy : Wcx;
        const int K = (mod == 0) ? K0 : (mod == 1 ? K1 : K2);

        const int nk  = (K + BK - 1) / BK;
        const int per = (nk + SPLIT - 1) / SPLIT;
        const int i0  = sp * per;
        const int i1  = min(nk, i0 + per);
        const int n   = i1 - i0;
        if (n <= 0) { __syncthreads(); continue; }

        float acc[4][8][4];
#pragma unroll
        for (int a = 0; a < 4; ++a)
#pragma unroll
            for (int b = 0; b < 8; ++b)
#pragma unroll
                for (int q = 0; q < 4; ++q) acc[a][b][q] = 0.f;

        // prologue: stages 0..2 (3 commit groups, possibly empty)
#pragma unroll
        for (int s = 0; s < STG - 1; ++s) {
            if (s < n) load_stage(A, W, K, mt, (i0 + s) * BK,
                                  As + s * AST, Bs + s * BST, tid);
            asm volatile("cp.async.commit_group;" ::: "memory");
        }
        // stage 0 ready (<=2 pending of 3 commits); preload held frags (g0)
        asm volatile("cp.async.wait_group 2;" ::: "memory");
        __syncthreads();

        uint32_t haf[4][4], hbf[8][2];
        frag_load(As, Bs, wm, wn, r, cq, haf, hbf);

#pragma unroll 1
        for (int it = 0; it < n; ++it) {
            // stages <= it+1 complete (commits = 3 + it, pending <= 1)
            asm volatile("cp.async.wait_group 1;" ::: "memory");
            __syncthreads();

            if (it + STG - 1 < n) {
                const int ws = (it + STG - 1) % STG;
                load_stage(A, W, K, mt, (i0 + it + STG - 1) * BK,
                           As + ws * AST, Bs + ws * BST, tid);
            }
            asm volatile("cp.async.commit_group;" ::: "memory");

            const int s  = it % STG;
            const int sn = ((it + 1 < n) ? (it + 1) : (n - 1)) % STG;

            // group 0 of stage it: MMA from held registers (no LDS on the
            // critical path right after the barrier)
            frag_mma(acc, haf, hbf);

            // group 1 of stage it: load + cvt + MMA
            {
                uint32_t af[4][4], bf[8][2];
                frag_load(As + s * AST + AST16, Bs + s * BST + BST16,
                          wm, wn, r, cq, af, bf);
                frag_mma(acc, af, bf);
            }

            // prefetch held frags: group 0 of stage it+1 (smem resident);
            // LDS/cvt overlaps tensor-pipe drain of this iter's MMAs
            frag_load(As + sn * AST, Bs + sn * BST, wm, wn, r, cq, haf, hbf);
        }

        asm volatile("cp.async.wait_group 0;" ::: "memory");
        __syncthreads();

        float* Cb = &g_P[mod][0][0];
#pragma unroll
        for (int mi = 0; mi < 4; ++mi) {
            const int row = mt * BM + wm + mi * 16 + r;
#pragma unroll
            for (int ni = 0; ni < 8; ++ni) {
                const int col = nt * BN + wn + ni * 8 + cq * 2;
                float* p0 = Cb + (size_t)row * NCOLS + col;
                float* p1 = p0 + 8 * NCOLS;
                asm volatile("red.global.add.v2.f32 [%0], {%1, %2};"
                             :: "l"(p0), "f"(acc[mi][ni][0]), "f"(acc[mi][ni][1]) : "memory");
                asm volatile("red.global.add.v2.f32 [%0], {%1, %2};"
                             :: "l"(p1), "f"(acc[mi][ni][2]), "f"(acc[mi][ni][3]) : "memory");
            }
        }
    }
}

// ---------------------------------------------------------------------------
// block reduce (value valid on thread 0)
// ---------------------------------------------------------------------------
__device__ __forceinline__ float block_reduce_sum(float v, float* red) {
#pragma unroll
    for (int o = 16; o; o >>= 1) v += __shfl_xor_sync(0xffffffffu, v, o);
    const int t = threadIdx.x;
    __syncthreads();
    if ((t & 31) == 0) red[t >> 5] = v;
    __syncthreads();
    if (t == 0) {
        float s = 0.f;
#pragma unroll
        for (int i = 0; i < 8; ++i) s += red[i];
        v = s;
    }
    return v;
}

// ---------------------------------------------------------------------------
// Fused attention (R15 version, unchanged)
// ---------------------------------------------------------------------------
__global__ __launch_bounds__(256, 4)
void attn_kernel(const float* __restrict__ W3e,
                 const float* __restrict__ W3m,
                 const float* __restrict__ W3c,
                 const float* __restrict__ b3e,
                 const float* __restrict__ b3m,
                 const float* __restrict__ b3c,
                 float* __restrict__ out)
{
    const int b    = blockIdx.x;
    const int pair = blockIdx.y;
    const int t    = threadIdx.x;

    __shared__ float2  sa[MDIM];       // a-side, scaled by LOG2E
    __shared__ float2  sb[MDIM];       // b-side, unscaled
    __shared__ float   xbuf[256 * 17]; // col-transpose buffer (17-pad)
    __shared__ float   red[8];
    __shared__ __half2 pax[128], pay[128], pbx[128], pby[128], prinv[128];
    __shared__ int     sfl[2];         // [0]=slast [1]=szero

    const int ai = (pair == 2) ? 1 : 0;          // e,e,m
    const int bi = (pair == 0) ? 1 : 2;          // m,c,c

    {
        const float* Pa = &g_P[ai][b][0];
        float px = Pa[t], py = Pa[MDIM + t];
        float inv = rsqrtf(px * px + py * py) * LOG2E;
        sa[t] = make_float2(px * inv, py * inv);

        const float* Pb = &g_P[bi][b][0];
        px = Pb[t]; py = Pb[MDIM + t];
        inv = rsqrtf(px * px + py * py);
        sb[t] = make_float2(px * inv, py * inv);
    }
    __syncthreads();

    const __half2 hz = __float2half2_rn(0.f);

    if (pair < 2) {
        const int ti = t >> 4;        // row group
        const int tj = t & 15;        // col group

        __half2 bx2[8], by2[8];
#pragma unroll
        for (int k = 0; k < 8; ++k) {
            float2 b0 = sb[tj * 16 + 2 * k];
            float2 b1 = sb[tj * 16 + 2 * k + 1];
            bx2[k] = __floats2half2_rn(b0.x, b1.x);
            by2[k] = __floats2half2_rn(b0.y, b1.y);
        }

        __half2 cd2[8], cn02[8], cn12[8];
#pragma unroll
        for (int k = 0; k < 8; ++k) { cd2[k] = hz; cn02[k] = hz; cn12[k] = hz; }

        float rowd = 0.f, rown0 = 0.f, rown1 = 0.f;

#pragma unroll
        for (int ri = 0; ri < 16; ++ri) {
            const float2 av = sa[ti * 16 + ri];
            const __half2 ax2 = __float2half2_rn(av.x);
            const __half2 ay2 = __float2half2_rn(av.y);
            __half2 rd2 = hz, rn02 = hz, rn12 = hz;
#pragma unroll
            for (int k = 0; k < 8; ++k) {
                const __half2 d2 = __hfma2(ay2, by2[k], __hmul2(ax2, bx2[k]));
                const __half2 X2 = h2ex2(d2);
                cd2[k]  = __hadd2(cd2[k], X2);
                cn02[k] = __hfma2(ax2, X2, cn02[k]);
                cn12[k] = __hfma2(ay2, X2, cn12[k]);
                rd2  = __hadd2(rd2, X2);
                rn02 = __hfma2(bx2[k], X2, rn02);
                rn12 = __hfma2(by2[k], X2, rn12);
            }
            float2 f0 = __half22float2(rd2);
            float2 f1 = __half22float2(rn02);
            float2 f2 = __half22float2(rn12);
            float rd = f0.x + f0.y, rn0 = f1.x + f1.y, rn1 = f2.x + f2.y;
#pragma unroll
            for (int o = 1; o < 16; o <<= 1) {
                rd  += __shfl_xor_sync(0xffffffffu, rd,  o);
                rn0 += __shfl_xor_sync(0xffffffffu, rn0, o);
                rn1 += __shfl_xor_sync(0xffffffffu, rn1, o);
            }
            if (ri == tj) { rowd = rd; rown0 = rn0; rown1 = rn1; }
        }

        // ---- Direction B output (softmax over cols, weights=b): row = t
        {
            const float* WB = (pair == 0) ? W3m : W3c;
            float v = (rown0 * WB[t] + rown1 * WB[MDIM + t]) / rowd;
            v = block_reduce_sum(v, red);
            if (t == 0) {
                if (pair == 0) g_partial[1][0][b] = v;
                else           g_partial[2][0][b] = v;
            }
        }

        // ---- Direction A output (softmax over rows, weights=a): col = t
        float d = 0.f, n0 = 0.f, n1 = 0.f;
#pragma unroll 1
        for (int ph = 0; ph < 3; ++ph) {
            __syncthreads();
#pragma unroll
            for (int k = 0; k < 8; ++k) {
                const __half2 src = (ph == 0) ? cd2[k] : (ph == 1 ? cn02[k] : cn12[k]);
                const float2 f = __half22float2(src);
                xbuf[t * 17 + 2 * k]     = f.x;
                xbuf[t * 17 + 2 * k + 1] = f.y;
            }
            __syncthreads();
            float s = 0.f;
#pragma unroll
            for (int tp = 0; tp < 16; ++tp)
                s += xbuf[(tp * 16 + (t >> 4)) * 17 + (t & 15)];
            if (ph == 0) d = s; else if (ph == 1) n0 = s; else n1 = s;
        }
        {
            const float* WA = W3e + (pair == 0 ? 0 : 512);
            float v = LN2 * (n0 * WA[t] + n1 * WA[MDIM + t]) / d;
            v = block_reduce_sum(v, red);
            if (t == 0) g_partial[0][pair][b] = v;
        }
    } else {
        // pack half2 operand arrays (threads 0..127)
        if (t < 128) {
            float2 a0 = sa[2 * t], a1 = sa[2 * t + 1];
            pax[t] = __floats2half2_rn(a0.x, a1.x);
            pay[t] = __floats2half2_rn(a0.y, a1.y);
            float2 b0 = sb[2 * t], b1 = sb[2 * t + 1];
            pbx[t] = __floats2half2_rn(b0.x, b1.x);
            pby[t] = __floats2half2_rn(b0.y, b1.y);
        }
        __syncthreads();

        // ---- Pass 1: thread t = m-index. att_cm output + rinv
        {
            const __half2 ax2 = __float2half2_rn(sa[t].x);
            const __half2 ay2 = __float2half2_rn(sa[t].y);
            float d = 0.f, n0 = 0.f, n1 = 0.f;
#pragma unroll 2
            for (int ko = 0; ko < 16; ++ko) {
                __half2 d2 = hz, n02 = hz, n12 = hz;
#pragma unroll
                for (int ki = 0; ki < 8; ++ki) {
                    const int k = ko * 8 + ki;
                    const __half2 e2 = __hfma2(ay2, pby[k], __hmul2(ax2, pbx[k]));
                    const __half2 X2 = h2ex2(e2);
                    d2  = __hadd2(d2, X2);
                    n02 = __hfma2(pbx[k], X2, n02);
                    n12 = __hfma2(pby[k], X2, n12);
                }
                float2 f;
                f = __half22float2(d2);  d  += f.x + f.y;
                f = __half22float2(n02); n0 += f.x + f.y;
                f = __half22float2(n12); n1 += f.x + f.y;
            }
            const float id = 1.0f / d;
            reinterpret_cast<__half*>(prinv)[t] = __float2half(id);
            float v = (n0 * W3c[512 + t] + n1 * W3c[768 + t]) * id;
            v = block_reduce_sum(v, red);     // internal syncs publish prinv
            if (t == 0) g_partial[2][1][b] = v;
        }
        // ---- Pass 2: thread t = c-index. att_mc (weights = a, *LN2)
        {
            const __half2 cx2 = __float2half2_rn(sb[t].x);
            const __half2 cy2 = __float2half2_rn(sb[t].y);
            float n0 = 0.f, n1 = 0.f;
#pragma unroll 2
            for (int ko = 0; ko < 16; ++ko) {
                __half2 n02 = hz, n12 = hz;
#pragma unroll
                for (int ki = 0; ki < 8; ++ki) {
                    const int k = ko * 8 + ki;
                    const __half2 e2 = __hfma2(pay[k], cy2, __hmul2(pax[k], cx2));
                    const __half2 X2 = __hmul2(h2ex2(e2), prinv[k]);
                    n02 = __hfma2(pax[k], X2, n02);
                    n12 = __hfma2(pay[k], X2, n12);
                }
                float2 f;
                f = __half22float2(n02); n0 += f.x + f.y;
                f = __half22float2(n12); n1 += f.x + f.y;
            }
            float v = LN2 * (n0 * W3m[512 + t] + n1 * W3m[768 + t]);
            v = block_reduce_sum(v, red);
            if (t == 0) g_partial[1][1][b] = v;
        }
    }

    // ---- per-batch g_P re-zero (for next graph replay) + final head
    __syncthreads();            // all reads of g_P / writes of partials done
    __threadfence();
    if (t == 0) {
        sfl[1] = (atomicAdd(&g_bcnt[b], 1) == 2) ? 1 : 0;
        int tk = atomicAdd(&g_done, 1);
        sfl[0] = (tk == NUNITS - 1) ? 1 : 0;
    }
    __syncthreads();
    if (sfl[1]) {
        // all 3 units of batch b have finished their reads of g_P[*][b][*]
#pragma unroll
        for (int md = 0; md < 3; ++md) {
            float2* p = reinterpret_cast<float2*>(&g_P[md][b][0]);
            p[t] = make_float2(0.f, 0.f);
        }
        if (t == 0) g_bcnt[b] = 0;
    }
    if (sfl[0]) {
        __threadfence();
#pragma unroll
        for (int q = 0; q < 2; ++q) {
            const int bb = t + q * 256;
            const float xe = g_partial[0][0][bb] + g_partial[0][1][bb] + b3e[0];
            const float xm = g_partial[1][0][bb] + g_partial[1][1][bb] + b3m[0];
            const float xc = g_partial[2][0][bb] + g_partial[2][1][bb] + b3c[0];
            out[bb]             = 1.0f / (1.0f + expf(-xe));
            out[BATCH + bb]     = 1.0f / (1.0f + expf(-xm));
            out[2 * BATCH + bb] = 1.0f / (1.0f + expf(-xc));
        }
        if (t == 0) g_done = 0;   // reset for next graph replay
    }
}

// ---------------------------------------------------------------------------
// Launch
// ---------------------------------------------------------------------------
extern "C" void kernel_launch(void* const* d_in, const int* in_sizes, int n_in,
                              void* d_out, int out_size)
{
    const float* expr = (const float*)d_in[0];
    const float* mut  = (const float*)d_in[1];
    const float* cna  = (const float*)d_in[2];
    const float* Wex  = (const float*)d_in[3];
    const float* Wey  = (const float*)d_in[4];
    const float* Wmx  = (const float*)d_in[5];
    const float* Wmy  = (const float*)d_in[6];
    const float* Wcx  = (const float*)d_in[7];
    const float* Wcy  = (const float*)d_in[8];
    const float* W3e  = (const float*)d_in[9];
    const float* b3e  = (const float*)d_in[10];
    const float* W3m  = (const float*)d_in[11];
    const float* b3m  = (const float*)d_in[12];
    const float* W3c  = (const float*)d_in[13];
    const float* b3c  = (const float*)d_in[14];

    const int K1 = in_sizes[0] / BATCH;   // 20000
    const int K2 = in_sizes[1] / BATCH;   // 15000
    const int K3 = in_sizes[2] / BATCH;   // 20000

    const int SMEM = STG * (AST + BST) * 4;   // 4 * 48KB = 196608 B
    static bool attr_set = false;
    if (!attr_set) {
        cudaFuncSetAttribute(gemm_mma, cudaFuncAttributeMaxDynamicSharedMemorySize, SMEM);
        attr_set = true;
    }

    gemm_mma<<<dim3(4, 2, SPLIT), NTHR, SMEM>>>(
        expr, mut, cna, Wex, Wey, Wmx, Wmy, Wcx, Wcy, K1, K2, K3);

    attn_kernel<<<dim3(BATCH, 3), 256>>>(W3e, W3m, W3c, b3e, b3m, b3c,
                                         (float*)d_out);
}